// round 16
// baseline (speedup 1.0000x reference)
#include <cuda_runtime.h>
#include <math.h>
#include <stdint.h>

#define NTOK 512
#define CSD 384
#define CZD 128
#define NH 12
#define PQN 4
#define PVN 8
#define NBLK 8
#define QKV_W 1152
#define CAT_W 2112
#define MNS (NTOK*CSD)
#define QOFF (NTOK*QKV_W)

#define WL 0.57735026918962576f             /* sqrt(1/3) */
#define HALFWC 0.11785113019775793f         /* 0.5*sqrt(2/(9*4)) */

// ---------------- device scratch ----------------
__device__ __align__(16) float d_s[NTOK*CSD];
__device__ __align__(16) float d_Wall[CSD*QKV_W];
__device__ __align__(16) float d_WallHi[CSD*QKV_W];
__device__ __align__(16) float d_WallLo[CSD*QKV_W];
__device__ __align__(16) float d_woutHi[CAT_W*CSD];
__device__ __align__(16) float d_woutLo[CAT_W*CSD];
__device__ __align__(16) float d_wtHi[3*CSD*CSD];
__device__ __align__(16) float d_wtLo[3*CSD*CSD];
__device__ __align__(16) float d_bT[(size_t)NH*NTOK*NTOK];   // [h][i][j], pre-scaled by wL
__device__ __align__(16) float d_a[(size_t)NH*NTOK*NTOK];    // [h][i][j] attn weights
__device__ __align__(16) float d_QfT[NH*32*NTOK];            // [h][f][i]
__device__ __align__(16) float d_KfT[NH*32*NTOK];            // [h][f][j]
__device__ __align__(16) float d_vJ[NH*NTOK*64];             // [h][j][d]
__device__ __align__(16) float d_cat[NTOK*CAT_W];
__device__ __align__(16) float d_part[6*NTOK*CSD];
__device__ __align__(16) float d_R[NTOK*9];
__device__ __align__(16) float d_t[NTOK*3];

// ---------------- init ----------------
__global__ void k_init(const float* __restrict__ s_in) {
    int idx = blockIdx.x*blockDim.x + threadIdx.x;
    if (idx < NTOK*CSD) d_s[idx] = s_in[idx];
    if (idx < NTOK*9)   d_R[idx] = ((idx % 9) % 4 == 0) ? 1.f : 0.f;
    if (idx < NTOK*3)   d_t[idx] = 0.f;
}

__global__ void k_catW(const float* __restrict__ wq, const float* __restrict__ wkv,
                       const float* __restrict__ wqp, const float* __restrict__ wkvp) {
    int idx = blockIdx.x*blockDim.x + threadIdx.x;
    if (idx >= CSD*QKV_W) return;
    int k = idx / QKV_W, c = idx % QKV_W;
    float v;
    if (c < 192)      v = wq[k*192 + c];
    else if (c < 576) v = wkv[k*384 + (c-192)];
    else if (c < 720) v = wqp[k*144 + (c-576)];
    else              v = wkvp[k*432 + (c-720)];
    d_Wall[idx] = v;
}

// split fp32 into tf32 hi/lo pair
__global__ void k_splitW(const float* __restrict__ src, float* __restrict__ hi,
                         float* __restrict__ lo, int n) {
    int i = blockIdx.x*blockDim.x + threadIdx.x;
    if (i >= n) return;
    float v = src[i];
    uint32_t hb; asm("cvt.rna.tf32.f32 %0, %1;" : "=r"(hb) : "f"(v));
    float hf = __uint_as_float(hb);
    float lf = v - hf;
    uint32_t lb; asm("cvt.rna.tf32.f32 %0, %1;" : "=r"(lb) : "f"(lf));
    hi[i] = hf;
    lo[i] = __uint_as_float(lb);
}

// b = wL * (z @ w_b), once per launch, layout [h][i][j]
__global__ void k_bT(const float* __restrict__ z, const float* __restrict__ wb) {
    int gwarp = (blockIdx.x*blockDim.x + threadIdx.x) >> 5;
    int lane  = threadIdx.x & 31;
    int nwarps = (gridDim.x*blockDim.x) >> 5;
    float wreg[4][NH];
    #pragma unroll
    for (int k = 0; k < 4; k++)
        #pragma unroll
        for (int h = 0; h < NH; h++)
            wreg[k][h] = wb[(lane + 32*k)*NH + h];
    for (int row = gwarp; row < NTOK*NTOK; row += nwarps) {
        const float* zr = z + (size_t)row*CZD;
        float zv[4];
        #pragma unroll
        for (int k = 0; k < 4; k++) zv[k] = zr[lane + 32*k];
        float acc[NH];
        #pragma unroll
        for (int h = 0; h < NH; h++)
            acc[h] = zv[0]*wreg[0][h] + zv[1]*wreg[1][h] + zv[2]*wreg[2][h] + zv[3]*wreg[3][h];
        #pragma unroll
        for (int h = 0; h < NH; h++)
            #pragma unroll
            for (int o = 16; o; o >>= 1)
                acc[h] += __shfl_xor_sync(0xffffffffu, acc[h], o);
        if (lane == 0) {
            int i = row >> 9, j = row & 511;
            #pragma unroll
            for (int h = 0; h < NH; h++)
                d_bT[((size_t)h*NTOK + i)*NTOK + j] = WL * acc[h];
        }
    }
}

#define MMA_TF32(d, a, b) \
    asm volatile("mma.sync.aligned.m16n8k8.row.col.f32.tf32.tf32.f32 " \
                 "{%0,%1,%2,%3},{%4,%5,%6,%7},{%8,%9},{%0,%1,%2,%3};" \
                 : "+f"(d[0]),"+f"(d[1]),"+f"(d[2]),"+f"(d[3]) \
                 : "r"(a[0]),"r"(a[1]),"r"(a[2]),"r"(a[3]),"r"(b[0]),"r"(b[1]))

__device__ __forceinline__ void tf32split(float v, uint32_t& h, uint32_t& l) {
    uint32_t hb; asm("cvt.rna.tf32.f32 %0, %1;" : "=r"(hb) : "f"(v));
    float lf = v - __uint_as_float(hb);
    uint32_t lb; asm("cvt.rna.tf32.f32 %0, %1;" : "=r"(lb) : "f"(lf));
    h = hb; l = lb;
}

// A-operand loader: plain, or relu(sum of 3 split-K partials)
__device__ __forceinline__ float4 loadA4(const float* p, size_t off, int fuseRelu) {
    float4 a = *reinterpret_cast<const float4*>(p + off);
    if (fuseRelu) {
        float4 b = *reinterpret_cast<const float4*>(p + off + (size_t)MNS);
        float4 c = *reinterpret_cast<const float4*>(p + off + (size_t)2*MNS);
        a.x = fmaxf(a.x + b.x + c.x, 0.f);
        a.y = fmaxf(a.y + b.y + c.y, 0.f);
        a.z = fmaxf(a.z + b.z + c.z, 0.f);
        a.w = fmaxf(a.w + b.w + c.w, 0.f);
    }
    return a;
}

// ------- 3xTF32 tensor-core GEMM body on dynamic smem (9728 floats) -------
__device__ void mm3_body(float* sm, const float* A, const float* Bhi,
                         const float* Blo, float* Cb,
                         int bx, int by, int kbase,
                         int M, int N, int K, int Kp, int fuseRelu) {
    float (*Ah)[64][20] = (float(*)[64][20])(sm);
    float (*Al)[64][20] = (float(*)[64][20])(sm + 2560);
    float (*Bh)[16][72] = (float(*)[16][72])(sm + 5120);
    float (*Bl)[16][72] = (float(*)[16][72])(sm + 5120 + 2304);
    int tid = threadIdx.x;
    int lane = tid & 31, warp = tid >> 5;
    int g = lane >> 2, tig = lane & 3;
    int wm = (warp >> 2) * 32;
    int wn = (warp & 3) * 16;
    int row0 = by * 64, col0 = bx * 64;
    const float* Ab  = A   + (size_t)row0*K + kbase;
    const float* Bhb = Bhi + (size_t)kbase*N + col0;
    const float* Blb = Blo + (size_t)kbase*N + col0;

    int ar = tid >> 2, ac = (tid & 3)*4;
    int br = tid >> 4, bc = (tid & 15)*4;

    float4 aR = loadA4(Ab, (size_t)ar*K + ac, fuseRelu);
    float4 hR = *reinterpret_cast<const float4*>(&Bhb[(size_t)br*N + bc]);
    float4 lR = *reinterpret_cast<const float4*>(&Blb[(size_t)br*N + bc]);
    {
        float4 h4, l4;
        tf32split(aR.x, *(uint32_t*)&h4.x, *(uint32_t*)&l4.x);
        tf32split(aR.y, *(uint32_t*)&h4.y, *(uint32_t*)&l4.y);
        tf32split(aR.z, *(uint32_t*)&h4.z, *(uint32_t*)&l4.z);
        tf32split(aR.w, *(uint32_t*)&h4.w, *(uint32_t*)&l4.w);
        *reinterpret_cast<float4*>(&Ah[0][ar][ac]) = h4;
        *reinterpret_cast<float4*>(&Al[0][ar][ac]) = l4;
    }
    *reinterpret_cast<float4*>(&Bh[0][br][bc]) = hR;
    *reinterpret_cast<float4*>(&Bl[0][br][bc]) = lR;
    __syncthreads();

    float acc[2][2][4] = {};
    int KT = Kp >> 4;
    for (int kt = 0; kt < KT; kt++) {
        int cur = kt & 1;
        if (kt+1 < KT) {
            aR = loadA4(Ab, (size_t)ar*K + (kt+1)*16 + ac, fuseRelu);
            hR = *reinterpret_cast<const float4*>(&Bhb[(size_t)((kt+1)*16 + br)*N + bc]);
            lR = *reinterpret_cast<const float4*>(&Blb[(size_t)((kt+1)*16 + br)*N + bc]);
        }
        #pragma unroll
        for (int ks = 0; ks < 2; ks++) {
            int k0 = ks*8;
            uint32_t ahi[2][4], alo[2][4];
            #pragma unroll
            for (int mt = 0; mt < 2; mt++) {
                #pragma unroll
                for (int rr = 0; rr < 4; rr++) {
                    int rm = wm + mt*16 + g + (rr & 1)*8;
                    int rk = k0 + tig + (rr >> 1)*4;
                    ahi[mt][rr] = __float_as_uint(Ah[cur][rm][rk]);
                    alo[mt][rr] = __float_as_uint(Al[cur][rm][rk]);
                }
            }
            uint32_t bhf[2][2], blf[2][2];
            #pragma unroll
            for (int nt = 0; nt < 2; nt++) {
                int cn = wn + nt*8 + g;
                bhf[nt][0] = __float_as_uint(Bh[cur][k0 + tig][cn]);
                bhf[nt][1] = __float_as_uint(Bh[cur][k0 + tig + 4][cn]);
                blf[nt][0] = __float_as_uint(Bl[cur][k0 + tig][cn]);
                blf[nt][1] = __float_as_uint(Bl[cur][k0 + tig + 4][cn]);
            }
            #pragma unroll
            for (int mt = 0; mt < 2; mt++)
                #pragma unroll
                for (int nt = 0; nt < 2; nt++) {
                    MMA_TF32(acc[mt][nt], ahi[mt], bhf[nt]);
                    MMA_TF32(acc[mt][nt], ahi[mt], blf[nt]);
                    MMA_TF32(acc[mt][nt], alo[mt], bhf[nt]);
                }
        }
        if (kt+1 < KT) {
            int nxt = cur ^ 1;
            float4 h4, l4;
            tf32split(aR.x, *(uint32_t*)&h4.x, *(uint32_t*)&l4.x);
            tf32split(aR.y, *(uint32_t*)&h4.y, *(uint32_t*)&l4.y);
            tf32split(aR.z, *(uint32_t*)&h4.z, *(uint32_t*)&l4.z);
            tf32split(aR.w, *(uint32_t*)&h4.w, *(uint32_t*)&l4.w);
            *reinterpret_cast<float4*>(&Ah[nxt][ar][ac]) = h4;
            *reinterpret_cast<float4*>(&Al[nxt][ar][ac]) = l4;
            *reinterpret_cast<float4*>(&Bh[nxt][br][bc]) = hR;
            *reinterpret_cast<float4*>(&Bl[nxt][br][bc]) = lR;
        }
        __syncthreads();
    }
    #pragma unroll
    for (int mt = 0; mt < 2; mt++)
        #pragma unroll
        for (int nt = 0; nt < 2; nt++) {
            int r0 = row0 + wm + mt*16 + g;
            int c  = col0 + wn + nt*8 + 2*tig;
            *reinterpret_cast<float2*>(&Cb[(size_t)r0*N + c]) =
                make_float2(acc[mt][nt][0], acc[mt][nt][1]);
            *reinterpret_cast<float2*>(&Cb[(size_t)(r0+8)*N + c]) =
                make_float2(acc[mt][nt][2], acc[mt][nt][3]);
        }
}

__global__ void mm3(const float* __restrict__ A, const float* __restrict__ Bhi,
                    const float* __restrict__ Blo, float* __restrict__ C,
                    int M, int N, int K, int Kp, int kofs, int fuseRelu) {
    extern __shared__ float sm[];
    mm3_body(sm, A, Bhi, Blo, C + (size_t)blockIdx.z*M*N,
             blockIdx.x, blockIdx.y, blockIdx.z*Kp + kofs, M, N, K, Kp, fuseRelu);
}

// ---------------- point transform + feature build (sums 2 qkv split partials) ----------------
__global__ void k_transform(const float* __restrict__ hw) {
    int n = blockIdx.x;
    int tid = threadIdx.x;  // 128
    __shared__ float Rs[9], ts[3], sqk_s[NH], coef_s[NH];
    if (tid < 9)  Rs[tid] = d_R[n*9 + tid];
    if (tid < 3)  ts[tid] = d_t[n*3 + tid];
    if (tid < NH) {
        sqk_s[tid] = 0.f;
        float x = hw[tid];
        float g = (x > 20.f) ? x : log1pf(__expf(x));
        coef_s[tid] = g * HALFWC;
    }
    __syncthreads();
    const float* q0 = &d_part[(size_t)n*QKV_W];
    const float* q1 = &d_part[QOFF + (size_t)n*QKV_W];
    for (int l = tid; l < 192; l += 128) {
        int h = l >> 4, c = l & 15;
        d_QfT[(h*32 + c)*NTOK + n] = (q0[l] + q1[l]) * (0.25f*WL);
    }
    for (int l = tid; l < 384; l += 128) {
        int h = l >> 5, c = l & 31;
        float val = q0[192 + l] + q1[192 + l];
        if (c < 16) d_KfT[(h*32 + c)*NTOK + n] = val;
        else        d_vJ[((size_t)h*NTOK + n)*64 + (c-16)] = val;
    }
    for (int p = tid; p < 48; p += 128) {
        float x  = q0[576 + p*3 + 0] + q1[576 + p*3 + 0];
        float y  = q0[576 + p*3 + 1] + q1[576 + p*3 + 1];
        float zz = q0[576 + p*3 + 2] + q1[576 + p*3 + 2];
        float px = Rs[0]*x + Rs[1]*y + Rs[2]*zz + ts[0];
        float py = Rs[3]*x + Rs[4]*y + Rs[5]*zz + ts[1];
        float pz = Rs[6]*x + Rs[7]*y + Rs[8]*zz + ts[2];
        int h = p >> 2, pp = p & 3;
        float s2 = 2.f*WL*coef_s[h];
        d_QfT[(h*32 + 16 + pp*3 + 0)*NTOK + n] = px*s2;
        d_QfT[(h*32 + 16 + pp*3 + 1)*NTOK + n] = py*s2;
        d_QfT[(h*32 + 16 + pp*3 + 2)*NTOK + n] = pz*s2;
    }
    if (tid < NH) d_QfT[(tid*32 + 28)*NTOK + n] = 1.f;
    for (int p = tid; p < 144; p += 128) {
        float x  = q0[720 + p*3 + 0] + q1[720 + p*3 + 0];
        float y  = q0[720 + p*3 + 1] + q1[720 + p*3 + 1];
        float zz = q0[720 + p*3 + 2] + q1[720 + p*3 + 2];
        float px = Rs[0]*x + Rs[1]*y + Rs[2]*zz + ts[0];
        float py = Rs[3]*x + Rs[4]*y + Rs[5]*zz + ts[1];
        float pz = Rs[6]*x + Rs[7]*y + Rs[8]*zz + ts[2];
        int h = p / 12, pp = p % 12;
        if (pp < PQN) {
            d_KfT[(h*32 + 16 + pp*3 + 0)*NTOK + n] = px;
            d_KfT[(h*32 + 16 + pp*3 + 1)*NTOK + n] = py;
            d_KfT[(h*32 + 16 + pp*3 + 2)*NTOK + n] = pz;
            atomicAdd(&sqk_s[h], px*px + py*py + pz*pz);
        } else {
            int d = 16 + (pp - PQN)*3;
            size_t base = ((size_t)h*NTOK + n)*64 + d;
            d_vJ[base + 0] = px;
            d_vJ[base + 1] = py;
            d_vJ[base + 2] = pz;
        }
    }
    __syncthreads();
    if (tid < NH) d_KfT[(tid*32 + 28)*NTOK + n] = -WL*coef_s[tid]*sqk_s[tid];
}

// ======== fused logits + bT + softmax + A@V + o_pt back-transform ========
__global__ void k_lsmav() {
    extern __shared__ float sm[];
    float* as_s = sm;                      // 8192 floats
    float* Ksb  = sm + 8192;               // 4352 floats
    float* Qs   = sm + 8192 + 4352;        // 512 floats
    float* pt   = sm + 8192 + 4352 + 512;  // 384 floats
    int i0 = blockIdx.x * 16, h = blockIdx.y;
    int tid = threadIdx.x;          // 256
    int iloc = tid >> 4, jg = tid & 15;

    for (int l = tid; l < 512; l += 256)
        Qs[l] = d_QfT[(h*32 + (l >> 4))*NTOK + i0 + (l & 15)];
    int lf[8], lj[8];
    #pragma unroll
    for (int u = 0; u < 8; u++) {
        int l = tid + u*256;
        lf[u] = l >> 6; lj[u] = l & 63;
    }
    #pragma unroll
    for (int u = 0; u < 8; u++)
        Ksb[0*2176 + lf[u]*68 + lj[u]] = d_KfT[(h*32 + lf[u])*NTOK + lj[u]];
    __syncthreads();
    float lv[32];
    #pragma unroll
    for (int t = 0; t < 8; t++) {
        float kr[8];
        if (t < 7) {
            #pragma unroll
            for (int u = 0; u < 8; u++)
                kr[u] = d_KfT[(h*32 + lf[u])*NTOK + (t+1)*64 + lj[u]];
        }
        int cur = t & 1;
        float a0 = 0.f, a1 = 0.f, a2 = 0.f, a3 = 0.f;
        #pragma unroll
        for (int f = 0; f < 32; f++) {
            float qf = Qs[f*16 + iloc];
            float4 kv = *reinterpret_cast<const float4*>(&Ksb[cur*2176 + f*68 + jg*4]);
            a0 += qf*kv.x; a1 += qf*kv.y; a2 += qf*kv.z; a3 += qf*kv.w;
        }
        lv[t*4+0] = a0; lv[t*4+1] = a1; lv[t*4+2] = a2; lv[t*4+3] = a3;
        if (t < 7) {
            #pragma unroll
            for (int u = 0; u < 8; u++)
                Ksb[(cur ^ 1)*2176 + lf[u]*68 + lj[u]] = kr[u];
        }
        __syncthreads();
    }
    int i = i0 + iloc;
    size_t rowoff = ((size_t)h*NTOK + i)*NTOK;
    float m = -1e30f;
    #pragma unroll
    for (int t = 0; t < 8; t++) {
        float4 bt = *reinterpret_cast<const float4*>(&d_bT[rowoff + t*64 + jg*4]);
        lv[t*4+0] += bt.x; lv[t*4+1] += bt.y; lv[t*4+2] += bt.z; lv[t*4+3] += bt.w;
        m = fmaxf(m, fmaxf(fmaxf(lv[t*4+0], lv[t*4+1]), fmaxf(lv[t*4+2], lv[t*4+3])));
    }
    #pragma unroll
    for (int o = 8; o; o >>= 1) m = fmaxf(m, __shfl_xor_sync(0xffffffffu, m, o));
    float s = 0.f;
    #pragma unroll
    for (int q = 0; q < 32; q++) { lv[q] = __expf(lv[q] - m); s += lv[q]; }
    #pragma unroll
    for (int o = 8; o; o >>= 1) s += __shfl_xor_sync(0xffffffffu, s, o);
    float inv = 1.f / s;
    #pragma unroll
    for (int t = 0; t < 8; t++) {
        float4 o4 = make_float4(lv[t*4+0]*inv, lv[t*4+1]*inv, lv[t*4+2]*inv, lv[t*4+3]*inv);
        *reinterpret_cast<float4*>(&d_a[rowoff + t*64 + jg*4]) = o4;
        *reinterpret_cast<float4*>(&as_s[iloc*512 + t*64 + jg*4]) = o4;
    }
    __syncthreads();   // as_s complete; Ksb free for v tiles

    // ---- A@V phase ----
    const float4* Vb = reinterpret_cast<const float4*>(&d_vJ[(size_t)h*NTOK*64]);
    float4* vb0 = reinterpret_cast<float4*>(Ksb);
    float4* vb1 = vb0 + 512;
    vb0[tid]       = Vb[tid];
    vb0[256 + tid] = Vb[256 + tid];
    __syncthreads();
    int r = tid >> 4, q = tid & 15;
    float4 acc = make_float4(0.f, 0.f, 0.f, 0.f);
    for (int t = 0; t < 16; t++) {
        float4* curv = (t & 1) ? vb1 : vb0;
        float4 pre0, pre1;
        if (t < 15) {
            pre0 = Vb[(t+1)*512 + tid];
            pre1 = Vb[(t+1)*512 + 256 + tid];
        }
        if (q < 10) {
            #pragma unroll 8
            for (int jj = 0; jj < 32; jj++) {
                float av = as_s[r*512 + t*32 + jj];
                float4 v4 = curv[jj*16 + q];
                acc.x += av*v4.x; acc.y += av*v4.y; acc.z += av*v4.z; acc.w += av*v4.w;
            }
        }
        if (t < 15) {
            float4* nx = (t & 1) ? vb0 : vb1;
            nx[tid] = pre0;
            nx[256 + tid] = pre1;
        }
        __syncthreads();
    }
    int irow = i0 + r;
    if (q < 4) {
        *reinterpret_cast<float4*>(&d_cat[(size_t)irow*CAT_W + h*16 + q*4]) = acc;
    } else if (q < 10) {
        pt[r*24 + (q-4)*4 + 0] = acc.x;
        pt[r*24 + (q-4)*4 + 1] = acc.y;
        pt[r*24 + (q-4)*4 + 2] = acc.z;
        pt[r*24 + (q-4)*4 + 3] = acc.w;
    }
    __syncthreads();
    if (tid < 128) {
        int rr = tid >> 3, p = tid & 7;
        int ii = i0 + rr;
        float v0 = pt[rr*24 + p*3 + 0];
        float v1 = pt[rr*24 + p*3 + 1];
        float v2 = pt[rr*24 + p*3 + 2];
        const float* Rp = &d_R[ii*9];
        float t0 = d_t[ii*3+0], t1 = d_t[ii*3+1], t2 = d_t[ii*3+2];
        float gx = v0 - t0, gy = v1 - t1, gz = v2 - t2;
        float lx = Rp[0]*gx + Rp[3]*gy + Rp[6]*gz;
        float ly = Rp[1]*gx + Rp[4]*gy + Rp[7]*gz;
        float lz = Rp[2]*gx + Rp[5]*gy + Rp[8]*gz;
        float* cr = &d_cat[(size_t)ii*CAT_W];
        cr[192 + h*24 + p*3 + 0] = lx;
        cr[192 + h*24 + p*3 + 1] = ly;
        cr[192 + h*24 + p*3 + 2] = lz;
        cr[480 + h*8 + p] = sqrtf(lx*lx + ly*ly + lz*lz + 1e-8f);
    }
}

// ======== fat kernel: out-proj K[0,576) split-2 (96 blocks) + o_pair (512 blocks) ========
// both depend only on k_lsmav outputs; disjoint d_cat columns -> no race.
__global__ void k_opgem(const float* __restrict__ z, const float* __restrict__ Bhi,
                        const float* __restrict__ Blo, float* __restrict__ C) {
    extern __shared__ float smf[];
    int tid = threadIdx.x;  // 256

    if (blockIdx.x < 96) {
        int idx = blockIdx.x;
        int bx = idx % 6, by = (idx / 6) % 8, bz = idx / 48;
        mm3_body(smf, d_cat, Bhi, Blo, C + (size_t)(4 + bz)*MNS,
                 bx, by, bz*288, NTOK, CSD, CAT_W, 288, 0);
        return;
    }
    int i = blockIdx.x - 96;
    float* as = smf;                 // 6144 floats
    float4* zb0 = reinterpret_cast<float4*>(smf + 6144);
    float4* zb1 = zb0 + 1024;
    float4* as4 = reinterpret_cast<float4*>(as);
    const float4* asrc = reinterpret_cast<const float4*>(d_a);
    #pragma unroll
    for (int u = 0; u < 6; u++) {
        int l = tid + u*256;
        int hh = l >> 7, qq = l & 127;
        as4[hh*128 + qq] = asrc[(((size_t)hh*NTOK + i)*NTOK >> 2) + qq];
    }
    const float4* zsrc = reinterpret_cast<const float4*>(z + (size_t)i*NTOK*CZD);
    bool loader = (tid >= 128);
    int lt = tid - 128;
    if (loader) {
        #pragma unroll
        for (int u = 0; u < 8; u++) zb0[u*128 + lt] = zsrc[u*128 + lt];
    }
    __syncthreads();
    int lane = tid & 31, h0 = tid >> 5;
    float acc[3][4] = {};
    for (int t = 0; t < 16; t++) {
        float4* cur = (t & 1) ? zb1 : zb0;
        if (loader) {
            if (t < 15) {
                float4* nxt = (t & 1) ? zb0 : zb1;
                #pragma unroll
                for (int u = 0; u < 8; u++)
                    nxt[u*128 + lt] = zsrc[(size_t)(t+1)*1024 + u*128 + lt];
            }
        } else {
            int jt = t*32;
            #pragma unroll 4
            for (int jj = 0; jj < 32; jj++) {
                float4 zv = cur[jj*32 + lane];
                float a0 = as[(h0+0)*NTOK + jt + jj];
                float a1 = as[(h0+4)*NTOK + jt + jj];
                float a2 = as[(h0+8)*NTOK + jt + jj];
                acc[0][0] += a0*zv.x; acc[0][1] += a0*zv.y; acc[0][2] += a0*zv.z; acc[0][3] += a0*zv.w;
                acc[1][0] += a1*zv.x; acc[1][1] += a1*zv.y; acc[1][2] += a1*zv.z; acc[1][3] += a1*zv.w;
                acc[2][0] += a2*zv.x; acc[2][1] += a2*zv.y; acc[2][2] += a2*zv.z; acc[2][3] += a2*zv.w;
            }
        }
        __syncthreads();
    }
    if (!loader) {
        #pragma unroll
        for (int hh = 0; hh < 3; hh++) {
            int h = h0 + hh*4;
            *reinterpret_cast<float4*>(&d_cat[(size_t)i*CAT_W + 576 + h*CZD + lane*4]) =
                make_float4(acc[hh][0], acc[hh][1], acc[hh][2], acc[hh][3]);
        }
    }
}

// ---------------- s = LN(s + bias + sum_p part[p]) ----------------
__global__ void k_addln(const float* __restrict__ part, int P,
                        const float* __restrict__ bias,
                        const float* __restrict__ g, const float* __restrict__ b) {
    int i = blockIdx.x;
    int tid = threadIdx.x;  // 128
    __shared__ float red[4];
    float v[3];
    float sum = 0.f;
    #pragma unroll
    for (int k = 0; k < 3; k++) {
        int c = tid + k*128;
        float x = d_s[(size_t)i*CSD + c];
        if (bias) x += bias[c];
        for (int p = 0; p < P; p++) x += part[(size_t)p*MNS + (size_t)i*CSD + c];
        v[k] = x;
        sum += x;
    }
    #pragma unroll
    for (int o = 16; o; o >>= 1) sum += __shfl_xor_sync(0xffffffffu, sum, o);
    if ((tid & 31) == 0) red[tid >> 5] = sum;
    __syncthreads();
    float tot = red[tid & 3];
    #pragma unroll
    for (int o = 2; o; o >>= 1) tot += __shfl_xor_sync(0xffffffffu, tot, o);
    float mean = tot * (1.f/384.f);
    float var = 0.f;
    #pragma unroll
    for (int k = 0; k < 3; k++) { float d = v[k] - mean; var += d*d; }
    #pragma unroll
    for (int o = 16; o; o >>= 1) var += __shfl_xor_sync(0xffffffffu, var, o);
    __syncthreads();
    if ((tid & 31) == 0) red[tid >> 5] = var;
    __syncthreads();
    float tv = red[tid & 3];
    #pragma unroll
    for (int o = 2; o; o >>= 1) tv += __shfl_xor_sync(0xffffffffu, tv, o);
    float inv = rsqrtf(tv*(1.f/384.f) + 1e-5f);
    #pragma unroll
    for (int k = 0; k < 3; k++) {
        int c = tid + k*128;
        d_s[(size_t)i*CSD + c] = (v[k] - mean)*inv*g[c] + b[c];
    }
}

// ------- ln2 + fused backbone update -------
__global__ void k_addln_bb(const float* __restrict__ part, int P,
                           const float* __restrict__ g, const float* __restrict__ b,
                           const float* __restrict__ wbb, const float* __restrict__ bbb) {
    int i = blockIdx.x;
    int tid = threadIdx.x;  // 128
    __shared__ float red[4];
    __shared__ float red6[4][6];
    __shared__ float upd[6];
    float v[3];
    float sum = 0.f;
    #pragma unroll
    for (int k = 0; k < 3; k++) {
        int c = tid + k*128;
        float x = d_s[(size_t)i*CSD + c];
        for (int p = 0; p < P; p++) x += part[(size_t)p*MNS + (size_t)i*CSD + c];
        v[k] = x;
        sum += x;
    }
    #pragma unroll
    for (int o = 16; o; o >>= 1) sum += __shfl_xor_sync(0xffffffffu, sum, o);
    if ((tid & 31) == 0) red[tid >> 5] = sum;
    __syncthreads();
    float tot = red[tid & 3];
    #pragma unroll
    for (int o = 2; o; o >>= 1) tot += __shfl_xor_sync(0xffffffffu, tot, o);
    float mean = tot * (1.f/384.f);
    float var = 0.f;
    #pragma unroll
    for (int k = 0; k < 3; k++) { float d = v[k] - mean; var += d*d; }
    #pragma unroll
    for (int o = 16; o; o >>= 1) var += __shfl_xor_sync(0xffffffffu, var, o);
    __syncthreads();
    if ((tid & 31) == 0) red[tid >> 5] = var;
    __syncthreads();
    float tv = red[tid & 3];
    #pragma unroll
    for (int o = 2; o; o >>= 1) tv += __shfl_xor_sync(0xffffffffu, tv, o);
    float inv = rsqrtf(tv*(1.f/384.f) + 1e-5f);
    float sv[3];
    #pragma unroll
    for (int k = 0; k < 3; k++) {
        int c = tid + k*128;
        sv[k] = (v[k] - mean)*inv*g[c] + b[c];
        d_s[(size_t)i*CSD + c] = sv[k];
    }
    float a6[6];
    #pragma unroll
    for (int o = 0; o < 6; o++) {
        a6[o] = sv[0]*wbb[(tid      )*6 + o]
              + sv[1]*wbb[(tid + 128)*6 + o]
              + sv[2]*wbb[(tid + 256)*6 + o];
    }
    #pragma unroll
    for (int o = 0; o < 6; o++)
        #pragma unroll
        for (int off = 16; off; off >>= 1)
            a6[o] += __shfl_xor_sync(0xffffffffu, a6[o], off);
    if ((tid & 31) == 0) {
        #pragma unroll
        for (int o = 0; o < 6; o++) red6[tid >> 5][o] = a6[o];
    }
    __syncthreads();
    if (tid < 6) upd[tid] = red6[0][tid] + red6[1][tid] + red6[2][tid] + red6[3][tid] + bbb[tid];
    __syncthreads();
    if (tid == 0) {
        float qb = upd[0], qc = upd[1], qd = upd[2];
        float qi = rsqrtf(1.f + qb*qb + qc*qc + qd*qd);
        float w = qi, x = qb*qi, y = qc*qi, zq = qd*qi;
        float Ru[9];
        Ru[0] = 1.f - 2.f*(y*y + zq*zq); Ru[1] = 2.f*(x*y - w*zq);        Ru[2] = 2.f*(x*zq + w*y);
        Ru[3] = 2.f*(x*y + w*zq);        Ru[4] = 1.f - 2.f*(x*x + zq*zq); Ru[5] = 2.f*(y*zq - w*x);
        Ru[6] = 2.f*(x*zq - w*y);        Ru[7] = 2.f*(y*zq + w*x);        Ru[8] = 1.f - 2.f*(x*x + y*y);
        float Ro[9];
        #pragma unroll
        for (int k = 0; k < 9; k++) Ro[k] = d_R[i*9 + k];
        float tu0 = upd[3], tu1 = upd[4], tu2 = upd[5];
        #pragma unroll
        for (int r = 0; r < 3; r++)
            d_t[i*3 + r] += Ro[r*3+0]*tu0 + Ro[r*3+1]*tu1 + Ro[r*3+2]*tu2;
        #pragma unroll
        for (int r = 0; r < 3; r++)
            #pragma unroll
            for (int c = 0; c < 3; c++)
                d_R[i*9 + r*3 + c] = Ro[r*3+0]*Ru[0*3+c] + Ro[r*3+1]*Ru[1*3+c] + Ro[r*3+2]*Ru[2*3+c];
    }
}

// ---------------- final output [s | t] ----------------
__global__ void k_out(float* __restrict__ out) {
    int idx = blockIdx.x*blockDim.x + threadIdx.x;
    if (idx >= NTOK*387) return;
    int i = idx / 387, c = idx % 387;
    out[idx] = (c < 384) ? d_s[(size_t)i*CSD + c] : d_t[i*3 + (c - 384)];
}

// ---------------- host ----------------
extern "C" void kernel_launch(void* const* d_in, const int* in_sizes, int n_in,
                              void* d_out, int out_size) {
    (void)in_sizes; (void)n_in; (void)out_size;
    const float* s     = (const float*)d_in[0];
    const float* z     = (const float*)d_in[1];
    const float* wq    = (const float*)d_in[2];
    const float* wkv   = (const float*)d_in[3];
    const float* wqp   = (const float*)d_in[4];
    const float* wkvp  = (const float*)d_in[5];
    const float* wb    = (const float*)d_in[6];
    const float* hw    = (const float*)d_in[7];
    const float* wout  = (const float*)d_in[8];
    const float* bout  = (const float*)d_in[9];
    const float* ln1g  = (const float*)d_in[10];
    const float* ln1b  = (const float*)d_in[11];
    const float* wt1   = (const float*)d_in[12];
    const float* wt2   = (const float*)d_in[13];
    const float* wt3   = (const float*)d_in[14];
    const float* ln2g  = (const float*)d_in[15];
    const float* ln2b  = (const float*)d_in[16];
    const float* wbb   = (const float*)d_in[17];
    const float* bbb   = (const float*)d_in[18];

    float *p_s, *p_Wall, *p_cat, *p_part;
    float *p_WallHi, *p_WallLo, *p_woutHi, *p_woutLo, *p_wtHi, *p_wtLo;
    cudaGetSymbolAddress((void**)&p_s,      d_s);
    cudaGetSymbolAddress((void**)&p_Wall,   d_Wall);
    cudaGetSymbolAddress((void**)&p_cat,    d_cat);
    cudaGetSymbolAddress((void**)&p_part,   d_part);
    cudaGetSymbolAddress((void**)&p_WallHi, d_WallHi);
    cudaGetSymbolAddress((void**)&p_WallLo, d_WallLo);
    cudaGetSymbolAddress((void**)&p_woutHi, d_woutHi);
    cudaGetSymbolAddress((void**)&p_woutLo, d_woutLo);
    cudaGetSymbolAddress((void**)&p_wtHi,   d_wtHi);
    cudaGetSymbolAddress((void**)&p_wtLo,   d_wtLo);

    cudaFuncSetAttribute(k_lsmav, cudaFuncAttributeMaxDynamicSharedMemorySize, 53760);
    cudaFuncSetAttribute(k_opgem, cudaFuncAttributeMaxDynamicSharedMemorySize, 57344);

    k_init<<<(NTOK*CSD + 255)/256, 256>>>(s);
    k_catW<<<(CSD*QKV_W + 255)/256, 256>>>(wq, wkv, wqp, wkvp);
    k_splitW<<<(CSD*QKV_W + 255)/256, 256>>>(p_Wall, p_WallHi, p_WallLo, CSD*QKV_W);
    k_splitW<<<(CAT_W*CSD + 255)/256, 256>>>(wout, p_woutHi, p_woutLo, CAT_W*CSD);
    k_splitW<<<(CSD*CSD + 255)/256, 256>>>(wt1, p_wtHi,             p_wtLo,             CSD*CSD);
    k_splitW<<<(CSD*CSD + 255)/256, 256>>>(wt2, p_wtHi + CSD*CSD,   p_wtLo + CSD*CSD,   CSD*CSD);
    k_splitW<<<(CSD*CSD + 255)/256, 256>>>(wt3, p_wtHi + 2*CSD*CSD, p_wtLo + 2*CSD*CSD, CSD*CSD);
    k_bT<<<512, 256>>>(z, wb);

    for (int it = 0; it < NBLK; it++) {
        // qkv/points projection: K=384 split 2 -> 288 blocks
        mm3<<<dim3(QKV_W/64, NTOK/64, 2), 256, 38912>>>(p_s, p_WallHi, p_WallLo, p_part,
                                                        NTOK, QKV_W, CSD, CSD/2, 0, 0);
        k_transform<<<NTOK, 128>>>(hw);
        // fused logits/softmax/A@V/o_pt: 384 blocks
        k_lsmav<<<dim3(32, NH), 256, 53760>>>();
        // fat: out-proj K[0,576) (96 blocks, slots 4-5) + o_pair (512 blocks)
        k_opgem<<<96 + NTOK, 256, 57344>>>(z, p_woutHi, p_woutLo, p_part);
        // out-proj rest: K[576,2112) split 4 -> slots 0-3
        mm3<<<dim3(CSD/64, NTOK/64, 4), 256, 38912>>>(p_cat, p_woutHi, p_woutLo, p_part,
                                                      NTOK, CSD, CAT_W, 384, 576, 0);
        k_addln<<<NTOK, 128>>>(p_part, 6, bout, ln1g, ln1b);
        // transition: t1 plain, t2/t3 fused relu-of-3-partials A-load
        mm3<<<dim3(CSD/64, NTOK/64, 3), 256, 38912>>>(p_s, p_wtHi, p_wtLo, p_part,
                                                      NTOK, CSD, CSD, CSD/3, 0, 0);
        mm3<<<dim3(CSD/64, NTOK/64, 3), 256, 38912>>>(p_part, p_wtHi + CSD*CSD, p_wtLo + CSD*CSD,
                                                      p_part + (size_t)3*MNS,
                                                      NTOK, CSD, CSD, CSD/3, 0, 1);
        mm3<<<dim3(CSD/64, NTOK/64, 3), 256, 38912>>>(p_part + (size_t)3*MNS,
                                                      p_wtHi + 2*CSD*CSD, p_wtLo + 2*CSD*CSD, p_part,
                                                      NTOK, CSD, CSD, CSD/3, 0, 1);
        k_addln_bb<<<NTOK, 128>>>(p_part, 3, ln2g, ln2b, wbb, bbb);
    }
    k_out<<<(NTOK*387 + 255)/256, 256>>>((float*)d_out);
}